// round 14
// baseline (speedup 1.0000x reference)
#include <cuda_runtime.h>

#define IMG_H 256
#define IMG_W 256
#define KS    33
#define PADV  16
#define TX    32
#define TY    8
#define VEC   4                      // pixels per thread (float4 weight loads)
#define TILE_W (TX * VEC)            // 128
#define PW2   (TILE_W + KS - 1)      // 160 patch width
#define PLANE (IMG_H * IMG_W)        // 65536

#define PH_SUB TY                    // fh fixed per CTA -> 8 patch rows

__global__ void zero_out_kernel(float* __restrict__ out)
{
    int i = blockIdx.x * blockDim.x + threadIdx.x;
    ((float4*)out)[i] = make_float4(0.f, 0.f, 0.f, 0.f);
}

__global__ __launch_bounds__(TX * TY)
void reblur_dynconv_z33_kernel(const float* __restrict__ img,
                               const float* __restrict__ ker,
                               float* __restrict__ out)
{
    __shared__ float s0[PH_SUB * PW2];
    __shared__ float s1[PH_SUB * PW2];
    __shared__ float s2[PH_SUB * PW2];

    const int lx  = threadIdx.x;
    const int ly  = threadIdx.y;
    const int tid = ly * TX + lx;
    const int bx0 = blockIdx.x * TILE_W;
    const int by0 = blockIdx.y * TY;
    const int fh  = blockIdx.z;              // single kernel row per CTA

    // Stage replication-padded rows [by0+fh-PAD, +8) x [bx0-PAD, +160), 3 ch.
    // Image is 768 KB -> these all hit L2.
    for (int i = tid; i < PH_SUB * PW2; i += TX * TY) {
        const int py = i / PW2;
        const int px = i - py * PW2;
        int gy = by0 + fh + py - PADV;
        int gx = bx0 + px - PADV;
        gy = gy < 0 ? 0 : (gy > IMG_H - 1 ? IMG_H - 1 : gy);
        gx = gx < 0 ? 0 : (gx > IMG_W - 1 ? IMG_W - 1 : gx);
        const int gi = gy * IMG_W + gx;
        s0[i] = img[gi];
        s1[i] = img[PLANE + gi];
        s2[i] = img[2 * PLANE + gi];
    }
    __syncthreads();

    const int x0  = bx0 + lx * VEC;
    const int y   = by0 + ly;
    const int pix = y * IMG_W + x0;
    // Weights for taps (fh, fw): planes fh*33 + fw, fw = 0..32, stride PLANE.
    const float* __restrict__ kr = ker + (size_t)(fh * KS) * PLANE + pix;

    // fh fixed -> each thread reads only its own smem row (sliding window).
    const float* __restrict__ r0 = &s0[ly * PW2 + lx * VEC];
    const float* __restrict__ r1 = &s1[ly * PW2 + lx * VEC];
    const float* __restrict__ r2 = &s2[ly * PW2 + lx * VEC];

    float a00 = 0.f, a01 = 0.f, a02 = 0.f, a03 = 0.f;
    float a10 = 0.f, a11 = 0.f, a12 = 0.f, a13 = 0.f;
    float a20 = 0.f, a21 = 0.f, a22 = 0.f, a23 = 0.f;

    // Plain unrolled tap loop (R7 codegen: ~43 regs, ptxas-pipelined LDG.128).
    #pragma unroll
    for (int fw = 0; fw < KS; ++fw) {
        float4 w = *(const float4*)&kr[(size_t)fw * PLANE];
        w.x = (w.x > 1e-4f) ? w.x : 0.0f;
        w.y = (w.y > 1e-4f) ? w.y : 0.0f;
        w.z = (w.z > 1e-4f) ? w.z : 0.0f;
        w.w = (w.w > 1e-4f) ? w.w : 0.0f;

        a00 = fmaf(w.x, r0[fw    ], a00);
        a01 = fmaf(w.y, r0[fw + 1], a01);
        a02 = fmaf(w.z, r0[fw + 2], a02);
        a03 = fmaf(w.w, r0[fw + 3], a03);

        a10 = fmaf(w.x, r1[fw    ], a10);
        a11 = fmaf(w.y, r1[fw + 1], a11);
        a12 = fmaf(w.z, r1[fw + 2], a12);
        a13 = fmaf(w.w, r1[fw + 3], a13);

        a20 = fmaf(w.x, r2[fw    ], a20);
        a21 = fmaf(w.y, r2[fw + 1], a21);
        a22 = fmaf(w.z, r2[fw + 2], a22);
        a23 = fmaf(w.w, r2[fw + 3], a23);
    }

    atomicAdd(&out[pix    ], a00);
    atomicAdd(&out[pix + 1], a01);
    atomicAdd(&out[pix + 2], a02);
    atomicAdd(&out[pix + 3], a03);

    atomicAdd(&out[PLANE + pix    ], a10);
    atomicAdd(&out[PLANE + pix + 1], a11);
    atomicAdd(&out[PLANE + pix + 2], a12);
    atomicAdd(&out[PLANE + pix + 3], a13);

    atomicAdd(&out[2 * PLANE + pix    ], a20);
    atomicAdd(&out[2 * PLANE + pix + 1], a21);
    atomicAdd(&out[2 * PLANE + pix + 2], a22);
    atomicAdd(&out[2 * PLANE + pix + 3], a23);
}

extern "C" void kernel_launch(void* const* d_in, const int* in_sizes, int n_in,
                              void* d_out, int out_size)
{
    const float* img = (const float*)d_in[0];   // [1,3,256,256]
    const float* ker = (const float*)d_in[1];   // [1,1089,256,256]
    float* out = (float*)d_out;                 // [1,3,256,256]

    zero_out_kernel<<<(3 * PLANE / 4) / 256, 256>>>(out);

    dim3 block(TX, TY);
    dim3 grid(IMG_W / TILE_W, IMG_H / TY, KS);  // 2 x 32 x 33 = 2112 CTAs
    reblur_dynconv_z33_kernel<<<grid, block>>>(img, ker, out);
}

// round 15
// speedup vs baseline: 1.2677x; 1.2677x over previous
#include <cuda_runtime.h>

#define IMG_H 256
#define IMG_W 256
#define KS    33
#define PADV  16
#define TX    32
#define TY    8
#define VEC   2                      // pixels per thread (float2 weight loads)
#define TILE_W (TX * VEC)            // 64
#define PW2   (TILE_W + KS - 1)      // 96 patch width
#define PLANE (IMG_H * IMG_W)        // 65536

#define PH_SUB TY                    // fh fixed per CTA -> 8 patch rows

__global__ void zero_out_kernel(float* __restrict__ out)
{
    int i = blockIdx.x * blockDim.x + threadIdx.x;
    ((float4*)out)[i] = make_float4(0.f, 0.f, 0.f, 0.f);
}

__global__ __launch_bounds__(TX * TY, 6)
void reblur_dynconv_v2_kernel(const float* __restrict__ img,
                              const float* __restrict__ ker,
                              float* __restrict__ out)
{
    __shared__ float s0[PH_SUB * PW2];
    __shared__ float s1[PH_SUB * PW2];
    __shared__ float s2[PH_SUB * PW2];

    const int lx  = threadIdx.x;
    const int ly  = threadIdx.y;
    const int tid = ly * TX + lx;
    const int bx0 = blockIdx.x * TILE_W;
    const int by0 = blockIdx.y * TY;
    const int fh  = blockIdx.z;              // single kernel row per CTA

    // Stage replication-padded rows [by0+fh-PAD, +8) x [bx0-PAD, +96), 3 ch.
    // 768 floats = exactly 3 strided iterations. Image is 768 KB -> L2 hits.
    #pragma unroll
    for (int k = 0; k < (PH_SUB * PW2) / (TX * TY); ++k) {
        const int i  = k * (TX * TY) + tid;
        const int py = i / PW2;
        const int px = i - py * PW2;
        int gy = by0 + fh + py - PADV;
        int gx = bx0 + px - PADV;
        gy = gy < 0 ? 0 : (gy > IMG_H - 1 ? IMG_H - 1 : gy);
        gx = gx < 0 ? 0 : (gx > IMG_W - 1 ? IMG_W - 1 : gx);
        const int gi = gy * IMG_W + gx;
        s0[i] = img[gi];
        s1[i] = img[PLANE + gi];
        s2[i] = img[2 * PLANE + gi];
    }
    __syncthreads();

    const int x0  = bx0 + lx * VEC;
    const int y   = by0 + ly;
    const int pix = y * IMG_W + x0;
    // Weights for taps (fh, fw): planes fh*33 + fw, fw = 0..32, stride PLANE.
    const float* __restrict__ kr = ker + (size_t)(fh * KS) * PLANE + pix;

    // fh fixed -> each thread reads only its own smem row (sliding window).
    const float* __restrict__ r0 = &s0[ly * PW2 + lx * VEC];
    const float* __restrict__ r1 = &s1[ly * PW2 + lx * VEC];
    const float* __restrict__ r2 = &s2[ly * PW2 + lx * VEC];

    float a00 = 0.f, a01 = 0.f;     // channel 0, px 0..1
    float a10 = 0.f, a11 = 0.f;     // channel 1
    float a20 = 0.f, a21 = 0.f;     // channel 2

    #pragma unroll
    for (int fw = 0; fw < KS; ++fw) {
        float2 w = *(const float2*)&kr[(size_t)fw * PLANE];  // 256B/warp, coalesced
        w.x = (w.x > 1e-4f) ? w.x : 0.0f;
        w.y = (w.y > 1e-4f) ? w.y : 0.0f;

        a00 = fmaf(w.x, r0[fw    ], a00);
        a01 = fmaf(w.y, r0[fw + 1], a01);

        a10 = fmaf(w.x, r1[fw    ], a10);
        a11 = fmaf(w.y, r1[fw + 1], a11);

        a20 = fmaf(w.x, r2[fw    ], a20);
        a21 = fmaf(w.y, r2[fw + 1], a21);
    }

    atomicAdd(&out[pix    ], a00);
    atomicAdd(&out[pix + 1], a01);

    atomicAdd(&out[PLANE + pix    ], a10);
    atomicAdd(&out[PLANE + pix + 1], a11);

    atomicAdd(&out[2 * PLANE + pix    ], a20);
    atomicAdd(&out[2 * PLANE + pix + 1], a21);
}

extern "C" void kernel_launch(void* const* d_in, const int* in_sizes, int n_in,
                              void* d_out, int out_size)
{
    const float* img = (const float*)d_in[0];   // [1,3,256,256]
    const float* ker = (const float*)d_in[1];   // [1,1089,256,256]
    float* out = (float*)d_out;                 // [1,3,256,256]

    zero_out_kernel<<<(3 * PLANE / 4) / 256, 256>>>(out);

    dim3 block(TX, TY);
    dim3 grid(IMG_W / TILE_W, IMG_H / TY, KS);  // 4 x 32 x 33 = 4224 CTAs
    reblur_dynconv_v2_kernel<<<grid, block>>>(img, ker, out);
}